// round 3
// baseline (speedup 1.0000x reference)
#include <cuda_runtime.h>
#include <math.h>

// ---------------------------------------------------------------------------
// Problem constants (fixed shapes)
// ---------------------------------------------------------------------------
#define B_   8
#define N_   4096
#define C_   512
#define NH_  8
#define HD_  64
#define MAXP_ 321
#define EPS_ 1e-6f
#define NSPLIT 8

// ---------------------------------------------------------------------------
// Scratch (device globals — no allocations allowed)
// ---------------------------------------------------------------------------
__device__ float g_QP[33554432];          // (B,NH,N,128): q_pos | q_neg   (134MB)
__device__ float g_KK[33554432];          // (B,NH,N,128): k_pos | k_neg   (134MB)
__device__ float g_V [16777216];          // (B,NH,N,64)                    (67MB)
__device__ float g_G [16777216];          // (B,N,C) gate                   (67MB)
__device__ float g_T [16777216];          // (B,N,C): xa, then (xa+vd)*g    (67MB)
__device__ float g_PART[512 * 128 * 65];  // partial kv sums                (17MB)
__device__ float g_KVALL[64 * 128 * 65];  // (bh, d, e) e<64: kv, e=64: mean
__device__ float g_sinv[C_];              // 1/softplus(scale_p)
__device__ float g_pw[C_];                // 1 + 4*sigmoid(power_p)

// ---------------------------------------------------------------------------
// Setup: per-channel scale / power
// ---------------------------------------------------------------------------
__global__ void setup_kernel(const float* __restrict__ scale_p,
                             const float* __restrict__ power_p) {
    int c = blockIdx.x * blockDim.x + threadIdx.x;
    if (c < C_) {
        g_sinv[c] = 1.0f / log1pf(expf(scale_p[c]));
        g_pw[c]   = 1.0f + 4.0f / (1.0f + expf(-power_p[c]));
    }
}

// ---------------------------------------------------------------------------
// GEMM 1: y = x @ [qg_w ; kv_w].T  (32768 x 2048), fused epilogue.
// 128x128 tile, BK=8, 256 threads, 8x8 microtile.
// Column segments: [0,512)=q, [512,1024)=g, [1024,1536)=k, [1536,2048)=v
// ---------------------------------------------------------------------------
__global__ __launch_bounds__(256, 2) void gemm_qgkv(
    const float* __restrict__ x, const float* __restrict__ qg_w,
    const float* __restrict__ kv_w, const float* __restrict__ pos_emb) {
    __shared__ float As[8][128];
    __shared__ float Bs[8][128];

    const int tid  = threadIdx.x;
    const int row0 = blockIdx.y * 128;
    const int col0 = blockIdx.x * 128;

    const float* __restrict__ Wp =
        (col0 < 1024) ? (qg_w + (size_t)col0 * C_)
                      : (kv_w + (size_t)(col0 - 1024) * C_);

    const int lr = tid >> 1;
    const int lk = (tid & 1) * 4;
    const float* xp = x  + (size_t)(row0 + lr) * C_ + lk;
    const float* wp = Wp + (size_t)lr * C_ + lk;

    const int ty = tid >> 4;
    const int tx = tid & 15;

    float acc[8][8];
#pragma unroll
    for (int i = 0; i < 8; i++)
#pragma unroll
        for (int j = 0; j < 8; j++) acc[i][j] = 0.f;

    for (int kt = 0; kt < C_; kt += 8) {
        float4 av = *(const float4*)(xp + kt);
        float4 bv = *(const float4*)(wp + kt);
        __syncthreads();
        As[lk + 0][lr] = av.x; As[lk + 1][lr] = av.y;
        As[lk + 2][lr] = av.z; As[lk + 3][lr] = av.w;
        Bs[lk + 0][lr] = bv.x; Bs[lk + 1][lr] = bv.y;
        Bs[lk + 2][lr] = bv.z; Bs[lk + 3][lr] = bv.w;
        __syncthreads();
#pragma unroll
        for (int k = 0; k < 8; k++) {
            float ar[8], br[8];
            *(float4*)&ar[0] = *(const float4*)&As[k][ty * 8];
            *(float4*)&ar[4] = *(const float4*)&As[k][ty * 8 + 4];
            *(float4*)&br[0] = *(const float4*)&Bs[k][tx * 8];
            *(float4*)&br[4] = *(const float4*)&Bs[k][tx * 8 + 4];
#pragma unroll
            for (int i = 0; i < 8; i++)
#pragma unroll
                for (int j = 0; j < 8; j++) acc[i][j] += ar[i] * br[j];
        }
    }

    const int seg  = col0 >> 9;          // 0:q 1:g 2:k 3:v
    const int coff = (col0 & 511) + tx * 8;

#pragma unroll
    for (int i = 0; i < 8; i++) {
        const int r = row0 + ty * 8 + i;
        const int b = r >> 12;
        const int n = r & 4095;
        if (seg == 0) {                       // ---- q ----
#pragma unroll
            for (int jj = 0; jj < 8; jj++) {
                const int c = coff + jj;
                const float v = acc[i][jj] * g_sinv[c];
                const float p = g_pw[c];
                const int h = c >> 6, d = c & 63;
                const size_t base = ((size_t)((b * NH_ + h) * N_ + n)) * 128;
                const float vp = fmaxf(v, 0.f), vn = fmaxf(-v, 0.f);
                g_QP[base + d]      = (vp > 0.f) ? __powf(vp, p) : 0.f;
                g_QP[base + 64 + d] = (vn > 0.f) ? __powf(vn, p) : 0.f;
            }
        } else if (seg == 1) {                // ---- g ----
#pragma unroll
            for (int jj = 0; jj < 8; jj++) {
                g_G[(size_t)r * C_ + coff + jj] = acc[i][jj];
            }
        } else if (seg == 2) {                // ---- k ----
            const int nm = n % MAXP_;
#pragma unroll
            for (int jj = 0; jj < 8; jj++) {
                const int c = coff + jj;
                const float v =
                    (acc[i][jj] + pos_emb[(size_t)nm * C_ + c]) * g_sinv[c];
                const float p = g_pw[c];
                const int h = c >> 6, d = c & 63;
                const size_t base = ((size_t)((b * NH_ + h) * N_ + n)) * 128;
                const float vp = fmaxf(v, 0.f), vn = fmaxf(-v, 0.f);
                g_KK[base + d]      = (vp > 0.f) ? __powf(vp, p) : 0.f;
                g_KK[base + 64 + d] = (vn > 0.f) ? __powf(vn, p) : 0.f;
            }
        } else {                              // ---- v ----
#pragma unroll
            for (int jj = 0; jj < 8; jj++) {
                const int c = coff + jj;
                const int h = c >> 6, d = c & 63;
                g_V[((size_t)((b * NH_ + h) * N_ + n)) * 64 + d] = acc[i][jj];
            }
        }
    }
}

// ---------------------------------------------------------------------------
// KV reduction (pass 1): per (bh, chunk) partial sums of kk^T @ [v | 1]
// grid: (NSPLIT, 64), 256 threads. Thread = (dg: 2 d-rows) x (eg: 16 e-cols)
// ---------------------------------------------------------------------------
__global__ __launch_bounds__(256) void kv_partial() {
    const int ch = blockIdx.x;
    const int bh = blockIdx.y;
    const int chunkN = N_ / NSPLIT;   // 512

    const float* KKp = g_KK + (size_t)bh * N_ * 128 + (size_t)ch * chunkN * 128;
    const float* Vp  = g_V  + (size_t)bh * N_ * 64  + (size_t)ch * chunkN * 64;

    __shared__ float skk[8][128];
    __shared__ float sv[8][64];

    const int t  = threadIdx.x;
    const int dg = t >> 2;
    const int eg = t & 3;
    const int d0 = dg * 2;
    const int eb = eg * 16;

    float acc0[16], acc1[16];
#pragma unroll
    for (int j = 0; j < 16; j++) { acc0[j] = 0.f; acc1[j] = 0.f; }
    float am0 = 0.f, am1 = 0.f;

    for (int n0 = 0; n0 < chunkN; n0 += 8) {
        __syncthreads();
        // load 8 rows of kk (1024 floats) and v (512 floats)
        *(float4*)&skk[t >> 5][(t * 4) & 127] =
            *(const float4*)&KKp[(size_t)(n0 + (t >> 5)) * 128 + ((t * 4) & 127)];
        if (t < 128) {
            *(float4*)&sv[t >> 4][(t * 4) & 63] =
                *(const float4*)&Vp[(size_t)(n0 + (t >> 4)) * 64 + ((t * 4) & 63)];
        }
        __syncthreads();
#pragma unroll
        for (int nn = 0; nn < 8; nn++) {
            const float2 k2 = *(const float2*)&skk[nn][d0];
            am0 += k2.x; am1 += k2.y;
#pragma unroll
            for (int j4 = 0; j4 < 4; j4++) {
                const float4 vv = *(const float4*)&sv[nn][eb + j4 * 4];
                acc0[j4 * 4 + 0] += k2.x * vv.x; acc1[j4 * 4 + 0] += k2.y * vv.x;
                acc0[j4 * 4 + 1] += k2.x * vv.y; acc1[j4 * 4 + 1] += k2.y * vv.y;
                acc0[j4 * 4 + 2] += k2.x * vv.z; acc1[j4 * 4 + 2] += k2.y * vv.z;
                acc0[j4 * 4 + 3] += k2.x * vv.w; acc1[j4 * 4 + 3] += k2.y * vv.w;
            }
        }
    }

    float* P = g_PART + (size_t)(bh * NSPLIT + ch) * (128 * 65);
#pragma unroll
    for (int j = 0; j < 16; j++) {
        P[(d0 + 0) * 65 + eb + j] = acc0[j];
        P[(d0 + 1) * 65 + eb + j] = acc1[j];
    }
    if (eg == 0) {
        P[(d0 + 0) * 65 + 64] = am0;
        P[(d0 + 1) * 65 + 64] = am1;
    }
}

// KV reduction (pass 2): deterministic sum of NSPLIT partials, * 1/N
__global__ __launch_bounds__(256) void kv_reduce() {
    const int bh = blockIdx.x;
    for (int idx = threadIdx.x; idx < 128 * 65; idx += 256) {
        float s = 0.f;
#pragma unroll
        for (int c = 0; c < NSPLIT; c++)
            s += g_PART[(size_t)(bh * NSPLIT + c) * (128 * 65) + idx];
        g_KVALL[(size_t)bh * (128 * 65) + idx] = s * (1.0f / (float)N_);
    }
}

// ---------------------------------------------------------------------------
// Apply attention: xa = [q_sim@kv1 * z1 , q_opp@kv2 * z2] -> g_T (B,N,C)
// q_opp[d] = q_sim[d^64].  grid: (16 n-chunks, 64 bh), 256 threads (1 row each)
// ---------------------------------------------------------------------------
__global__ __launch_bounds__(256) void attn_apply() {
    const int bh = blockIdx.y;
    const int b  = bh >> 3;
    const int h  = bh & 7;

    __shared__ float skv[128][68];   // 68-float stride: 272B = 16B-aligned rows
    for (int i = threadIdx.x; i < 128 * 65; i += 256) {
        const int d = i / 65, e = i % 65;
        skv[d][e] = g_KVALL[(size_t)bh * (128 * 65) + i];
    }
    __syncthreads();

    const int n = blockIdx.x * 256 + threadIdx.x;
    const float* Q = g_QP + ((size_t)bh * N_ + n) * 128;

    float accS[32], accO[32];
#pragma unroll
    for (int e = 0; e < 32; e++) { accS[e] = 0.f; accO[e] = 0.f; }
    float zs = 0.f, zo = 0.f;

    for (int d0 = 0; d0 < 64; d0 += 4) {
        float ql[4], qh[4];
        *(float4*)&ql[0] = *(const float4*)&Q[d0];
        *(float4*)&qh[0] = *(const float4*)&Q[d0 + 64];
#pragma unroll
        for (int dd = 0; dd < 4; dd++) {
            const int d = d0 + dd;
            const float a = ql[dd], bq = qh[dd];
            zs += a * skv[d][64]      + bq * skv[d + 64][64];
            zo += a * skv[d + 64][64] + bq * skv[d][64];
#pragma unroll
            for (int e4 = 0; e4 < 8; e4++) {
                const float4 v1 = *(const float4*)&skv[d][e4 * 4];
                const float4 v2 = *(const float4*)&skv[d + 64][e4 * 4];
                accS[e4 * 4 + 0] += a * v1.x + bq * v2.x;
                accS[e4 * 4 + 1] += a * v1.y + bq * v2.y;
                accS[e4 * 4 + 2] += a * v1.z + bq * v2.z;
                accS[e4 * 4 + 3] += a * v1.w + bq * v2.w;
                const float4 w1 = *(const float4*)&skv[d + 64][32 + e4 * 4];
                const float4 w2 = *(const float4*)&skv[d][32 + e4 * 4];
                accO[e4 * 4 + 0] += a * w1.x + bq * w2.x;
                accO[e4 * 4 + 1] += a * w1.y + bq * w2.y;
                accO[e4 * 4 + 2] += a * w1.z + bq * w2.z;
                accO[e4 * 4 + 3] += a * w1.w + bq * w2.w;
            }
        }
    }

    const float z1 = 1.0f / (zs + EPS_);
    const float z2 = 1.0f / (zo + EPS_);
    float* op = g_T + ((size_t)(b * N_ + n)) * C_ + h * 64;
#pragma unroll
    for (int e4 = 0; e4 < 8; e4++) {
        float4 o1 = make_float4(accS[e4 * 4 + 0] * z1, accS[e4 * 4 + 1] * z1,
                                accS[e4 * 4 + 2] * z1, accS[e4 * 4 + 3] * z1);
        *(float4*)&op[e4 * 4] = o1;
        float4 o2 = make_float4(accO[e4 * 4 + 0] * z2, accO[e4 * 4 + 1] * z2,
                                accO[e4 * 4 + 2] * z2, accO[e4 * 4 + 3] * z2);
        *(float4*)&op[32 + e4 * 4] = o2;
    }
}

// ---------------------------------------------------------------------------
// Depthwise 5x5 conv over (y=4096, x=8) per channel hw, fused with
// t = (xa + vd + bias) * g, written in-place into g_T.
// Conv input (hw,y,x) = V[b, hw>>3, ((hw&7)<<9) + (y>>3), ((y&7)<<3)+x]
// Output (hw,y,x) -> c = hw*8 + (y>>9), n_out = ((y&511)<<3)+x
// Block: (s-chunk of 64, hw, b): covers y = q*512 + s0+s for q in [0,8).
// ---------------------------------------------------------------------------
__global__ __launch_bounds__(128) void conv_fuse(const float* __restrict__ dwc_w,
                                                 const float* __restrict__ dwc_b) {
    const int b  = blockIdx.z;
    const int hw = blockIdx.y;
    const int s0 = blockIdx.x * 64;
    const int nh     = hw >> 3;
    const int base_n = (hw & 7) << 9;
    const int t = threadIdx.x;

    __shared__ float tile[8][68][12];
    __shared__ float wsm[25];
    __shared__ float outs[512][8];

    if (t < 25) wsm[t] = dwc_w[hw * 25 + t];

    // Load input tile: rows (q, sr), 12-wide with 2-col zero halo each side.
    for (int rid = t; rid < 8 * 68; rid += 128) {
        const int q  = rid / 68;
        const int sr = rid % 68;
        const int y  = q * 512 + s0 - 2 + sr;
        float* dst = &tile[q][sr][0];
        dst[0] = 0.f; dst[1] = 0.f; dst[10] = 0.f; dst[11] = 0.f;
        if (y >= 0 && y < N_) {
            const float* src =
                g_V + ((size_t)((b * NH_ + nh) * N_ + base_n + (y >> 3))) * 64 +
                ((y & 7) << 3);
#pragma unroll
            for (int xx = 0; xx < 8; xx++) dst[2 + xx] = src[xx];
        } else {
#pragma unroll
            for (int xx = 0; xx < 8; xx++) dst[2 + xx] = 0.f;
        }
    }
    __syncthreads();

    // Conv compute: thread = (q = t&7, sb = t>>3), 4 s-rows each, 8 x outputs.
    const int q  = t & 7;
    const int sb = t >> 3;
#pragma unroll
    for (int i = 0; i < 4; i++) {
        const int s = sb * 4 + i;
        float o[8];
#pragma unroll
        for (int x = 0; x < 8; x++) o[x] = 0.f;
#pragma unroll
        for (int ky = 0; ky < 5; ky++) {
            const float4* rp = (const float4*)&tile[q][s + ky][0];
            const float4 ra = rp[0], rb = rp[1], rc = rp[2];
            const float r[12] = {ra.x, ra.y, ra.z, ra.w, rb.x, rb.y,
                                 rb.z, rb.w, rc.x, rc.y, rc.z, rc.w};
#pragma unroll
            for (int kx = 0; kx < 5; kx++) {
                const float wv = wsm[ky * 5 + kx];
#pragma unroll
                for (int x = 0; x < 8; x++) o[x] += wv * r[x + kx];
            }
        }
#pragma unroll
        for (int x = 0; x < 8; x++) outs[s * 8 + x][q] = o[x];
    }
    __syncthreads();

    // Fused epilogue: t = (xa + vd + bias) * g, coalesced over (n_out, c).
    const float bias = dwc_b[hw];
    const size_t rowbase = ((size_t)b * N_ + (size_t)s0 * 8) * C_ + hw * 8;
#pragma unroll
    for (int k = 0; k < 32; k++) {
        const int idx = t + k * 128;
        const int nr = idx >> 3, q2 = idx & 7;
        const size_t gidx = rowbase + (size_t)nr * C_ + q2;
        g_T[gidx] = (g_T[gidx] + outs[nr][q2] + bias) * g_G[gidx];
    }
}

// ---------------------------------------------------------------------------
// GEMM 2: out = T @ proj_w.T + proj_b  (32768 x 512)
// ---------------------------------------------------------------------------
__global__ __launch_bounds__(256, 2) void gemm_proj(
    const float* __restrict__ proj_w, const float* __restrict__ proj_b,
    float* __restrict__ out) {
    __shared__ float As[8][128];
    __shared__ float Bs[8][128];

    const int tid  = threadIdx.x;
    const int row0 = blockIdx.y * 128;
    const int col0 = blockIdx.x * 128;

    const int lr = tid >> 1;
    const int lk = (tid & 1) * 4;
    const float* xp = g_T    + (size_t)(row0 + lr) * C_ + lk;
    const float* wp = proj_w + (size_t)(col0 + lr) * C_ + lk;

    const int ty = tid >> 4;
    const int tx = tid & 15;

    float acc[8][8];
#pragma unroll
    for (int i = 0; i < 8; i++)
#pragma unroll
        for (int j = 0; j < 8; j++) acc[i][j] = 0.f;

    for (int kt = 0; kt < C_; kt += 8) {
        float4 av = *(const float4*)(xp + kt);
        float4 bv = *(const float4*)(wp + kt);
        __syncthreads();
        As[lk + 0][lr] = av.x; As[lk + 1][lr] = av.y;
        As[lk + 2][lr] = av.z; As[lk + 3][lr] = av.w;
        Bs[lk + 0][lr] = bv.x; Bs[lk + 1][lr] = bv.y;
        Bs[lk + 2][lr] = bv.z; Bs[lk + 3][lr] = bv.w;
        __syncthreads();
#pragma unroll
        for (int k = 0; k < 8; k++) {
            float ar[8], br[8];
            *(float4*)&ar[0] = *(const float4*)&As[k][ty * 8];
            *(float4*)&ar[4] = *(const float4*)&As[k][ty * 8 + 4];
            *(float4*)&br[0] = *(const float4*)&Bs[k][tx * 8];
            *(float4*)&br[4] = *(const float4*)&Bs[k][tx * 8 + 4];
#pragma unroll
            for (int i = 0; i < 8; i++)
#pragma unroll
                for (int j = 0; j < 8; j++) acc[i][j] += ar[i] * br[j];
        }
    }

#pragma unroll
    for (int i = 0; i < 8; i++) {
        const int r = row0 + ty * 8 + i;
        float* orow = out + (size_t)r * C_ + col0 + tx * 8;
#pragma unroll
        for (int jj = 0; jj < 8; jj++) {
            orow[jj] = acc[i][jj] + proj_b[col0 + tx * 8 + jj];
        }
    }
}

// ---------------------------------------------------------------------------
// Launch
// ---------------------------------------------------------------------------
extern "C" void kernel_launch(void* const* d_in, const int* in_sizes, int n_in,
                              void* d_out, int out_size) {
    const float* x       = (const float*)d_in[0];
    const float* qg_w    = (const float*)d_in[1];
    const float* kv_w    = (const float*)d_in[2];
    const float* proj_w  = (const float*)d_in[3];
    const float* proj_b  = (const float*)d_in[4];
    const float* power_p = (const float*)d_in[5];
    const float* scale_p = (const float*)d_in[6];
    const float* pos_emb = (const float*)d_in[7];
    const float* dwc_w   = (const float*)d_in[8];
    const float* dwc_b   = (const float*)d_in[9];
    float* out = (float*)d_out;

    (void)in_sizes; (void)n_in; (void)out_size;

    setup_kernel<<<2, 256>>>(scale_p, power_p);
    gemm_qgkv<<<dim3(16, 256), 256>>>(x, qg_w, kv_w, pos_emb);
    kv_partial<<<dim3(NSPLIT, 64), 256>>>();
    kv_reduce<<<64, 256>>>();
    attn_apply<<<dim3(16, 64), 256>>>();
    conv_fuse<<<dim3(8, 64, 8), 128>>>(dwc_w, dwc_b);
    gemm_proj<<<dim3(4, 256), 256>>>(proj_w, proj_b, out);
}

// round 6
// speedup vs baseline: 1.7078x; 1.7078x over previous
#include <cuda_runtime.h>
#include <math.h>

// ---------------------------------------------------------------------------
// Problem constants (fixed shapes)
// ---------------------------------------------------------------------------
#define B_   8
#define N_   4096
#define C_   512
#define NH_  8
#define HD_  64
#define MAXP_ 321
#define EPS_ 1e-6f
#define NSPLIT 8

// ---------------------------------------------------------------------------
// Scratch (device globals — no allocations allowed)
// ---------------------------------------------------------------------------
__device__ float g_QP[33554432];          // (B,NH,N,128): q_pos | q_neg
__device__ float g_KK[33554432];          // (B,NH,N,128): k_pos | k_neg
__device__ float g_V [16777216];          // (B,NH,N,64)
__device__ float g_G [16777216];          // (B,N,C) gate
__device__ float g_T [16777216];          // (B,N,C): xa, then (xa+vd)*g
__device__ float g_PART[512 * 128 * 65];  // partial kv sums
__device__ float g_KVALL[64 * 128 * 65];  // (bh, d, e) e<64: kv, e=64: mean
__device__ float g_sinv[C_];              // 1/softplus(scale_p)
__device__ float g_pw[C_];                // 1 + 4*sigmoid(power_p)

// ---------------------------------------------------------------------------
// tf32 helpers
// ---------------------------------------------------------------------------
__device__ __forceinline__ unsigned f2tf(float f) {
    unsigned u;
    asm("cvt.rna.tf32.f32 %0, %1;" : "=r"(u) : "f"(f));
    return u;
}

__device__ __forceinline__ void mma_tf32(float c[4], unsigned a0, unsigned a1,
                                         unsigned a2, unsigned a3, unsigned b0,
                                         unsigned b1) {
    asm volatile(
        "mma.sync.aligned.m16n8k8.row.col.f32.tf32.tf32.f32 "
        "{%0,%1,%2,%3}, {%4,%5,%6,%7}, {%8,%9}, {%0,%1,%2,%3};"
        : "+f"(c[0]), "+f"(c[1]), "+f"(c[2]), "+f"(c[3])
        : "r"(a0), "r"(a1), "r"(a2), "r"(a3), "r"(b0), "r"(b1));
}

// ---------------------------------------------------------------------------
// Setup: per-channel scale / power
// ---------------------------------------------------------------------------
__global__ void setup_kernel(const float* __restrict__ scale_p,
                             const float* __restrict__ power_p) {
    int c = blockIdx.x * blockDim.x + threadIdx.x;
    if (c < C_) {
        g_sinv[c] = 1.0f / log1pf(expf(scale_p[c]));
        g_pw[c]   = 1.0f + 4.0f / (1.0f + expf(-power_p[c]));
    }
}

// ---------------------------------------------------------------------------
// Shared tf32 GEMM core (128x128 block, KT=16 double-buffered, 8 warps 64x32).
// Computes C[m][n] = sum_k A[row0+m][k] * W[col0+n][k], leaves result in
// c[4][4][4] fragments. Used by both big GEMMs via macro.
// ---------------------------------------------------------------------------
#define GEMM_CORE(Aptr, Wptr)                                                  \
    __shared__ unsigned As[2][128][20];                                        \
    __shared__ unsigned Bs[2][128][20];                                        \
    const int tid  = threadIdx.x;                                              \
    const int lane = tid & 31;                                                 \
    const int grp  = lane >> 2;                                                \
    const int tig  = lane & 3;                                                 \
    const int wid  = tid >> 5;                                                 \
    const int wm   = wid >> 2;                                                 \
    const int wn   = wid & 3;                                                  \
    const int sr   = tid >> 1;                                                 \
    const int sk   = (tid & 1) * 4;                                            \
    const float* aG = (Aptr) + (size_t)(row0 + sr) * C_ + sk;                  \
    const float* bG = (Wptr) + (size_t)sr * C_ + sk;                           \
    float c[4][4][4];                                                          \
    _Pragma("unroll") for (int i = 0; i < 4; i++)                              \
        _Pragma("unroll") for (int j = 0; j < 4; j++)                          \
            _Pragma("unroll") for (int l = 0; l < 4; l++) c[i][j][l] = 0.f;    \
    {                                                                          \
        float4 pa0 = *(const float4*)(aG);                                     \
        float4 pa1 = *(const float4*)(aG + 8);                                 \
        float4 pb0 = *(const float4*)(bG);                                     \
        float4 pb1 = *(const float4*)(bG + 8);                                 \
        *(uint4*)&As[0][sr][sk] =                                              \
            make_uint4(f2tf(pa0.x), f2tf(pa0.y), f2tf(pa0.z), f2tf(pa0.w));    \
        *(uint4*)&As[0][sr][sk + 8] =                                          \
            make_uint4(f2tf(pa1.x), f2tf(pa1.y), f2tf(pa1.z), f2tf(pa1.w));    \
        *(uint4*)&Bs[0][sr][sk] =                                              \
            make_uint4(f2tf(pb0.x), f2tf(pb0.y), f2tf(pb0.z), f2tf(pb0.w));    \
        *(uint4*)&Bs[0][sr][sk + 8] =                                          \
            make_uint4(f2tf(pb1.x), f2tf(pb1.y), f2tf(pb1.z), f2tf(pb1.w));    \
    }                                                                          \
    __syncthreads();                                                           \
    int buf = 0;                                                               \
    for (int kt = 0; kt < 32; kt++) {                                          \
        float4 pa0, pa1, pb0, pb1;                                             \
        if (kt < 31) {                                                         \
            pa0 = *(const float4*)(aG + (kt + 1) * 16);                        \
            pa1 = *(const float4*)(aG + (kt + 1) * 16 + 8);                    \
            pb0 = *(const float4*)(bG + (kt + 1) * 16);                        \
            pb1 = *(const float4*)(bG + (kt + 1) * 16 + 8);                    \
        }                                                                      \
        _Pragma("unroll") for (int ks = 0; ks < 2; ks++) {                     \
            unsigned af[4][4], bf[4][2];                                       \
            _Pragma("unroll") for (int mt = 0; mt < 4; mt++) {                 \
                const unsigned* p =                                            \
                    &As[buf][wm * 64 + mt * 16 + grp][ks * 8 + tig];           \
                af[mt][0] = p[0];                                              \
                af[mt][1] = p[160];                                            \
                af[mt][2] = p[4];                                              \
                af[mt][3] = p[164];                                            \
            }                                                                  \
            _Pragma("unroll") for (int nt = 0; nt < 4; nt++) {                 \
                const unsigned* p =                                            \
                    &Bs[buf][wn * 32 + nt * 8 + grp][ks * 8 + tig];            \
                bf[nt][0] = p[0];                                              \
                bf[nt][1] = p[4];                                              \
            }                                                                  \
            _Pragma("unroll") for (int mt = 0; mt < 4; mt++)                   \
                _Pragma("unroll") for (int nt = 0; nt < 4; nt++)               \
                    mma_tf32(c[mt][nt], af[mt][0], af[mt][1], af[mt][2],       \
                             af[mt][3], bf[nt][0], bf[nt][1]);                 \
        }                                                                      \
        if (kt < 31) {                                                         \
            *(uint4*)&As[buf ^ 1][sr][sk] = make_uint4(                        \
                f2tf(pa0.x), f2tf(pa0.y), f2tf(pa0.z), f2tf(pa0.w));           \
            *(uint4*)&As[buf ^ 1][sr][sk + 8] = make_uint4(                    \
                f2tf(pa1.x), f2tf(pa1.y), f2tf(pa1.z), f2tf(pa1.w));           \
            *(uint4*)&Bs[buf ^ 1][sr][sk] = make_uint4(                        \
                f2tf(pb0.x), f2tf(pb0.y), f2tf(pb0.z), f2tf(pb0.w));           \
            *(uint4*)&Bs[buf ^ 1][sr][sk + 8] = make_uint4(                    \
                f2tf(pb1.x), f2tf(pb1.y), f2tf(pb1.z), f2tf(pb1.w));           \
        }                                                                      \
        __syncthreads();                                                       \
        buf ^= 1;                                                              \
    }

// ---------------------------------------------------------------------------
// GEMM 1: y = x @ [qg_w ; kv_w].T  (32768 x 2048), fused nonlinear epilogue.
// Column segments: [0,512)=q, [512,1024)=g, [1024,1536)=k, [1536,2048)=v
// ---------------------------------------------------------------------------
__global__ __launch_bounds__(256) void gemm_qgkv(
    const float* __restrict__ x, const float* __restrict__ qg_w,
    const float* __restrict__ kv_w, const float* __restrict__ pos_emb) {
    const int row0 = blockIdx.y * 128;
    const int col0 = blockIdx.x * 128;
    const float* __restrict__ Wp =
        (col0 < 1024) ? (qg_w + (size_t)col0 * C_)
                      : (kv_w + (size_t)(col0 - 1024) * C_);

    GEMM_CORE(x, Wp)

    const int seg   = col0 >> 9;  // 0:q 1:g 2:k 3:v
    const int cbase = (col0 & 511) + wn * 32;

    // per-thread columns: cl[nt][j]
    float sv[4][2], pp[4][2];
    int ch[4][2], cd[4][2];
#pragma unroll
    for (int nt = 0; nt < 4; nt++)
#pragma unroll
        for (int j = 0; j < 2; j++) {
            const int cl = cbase + nt * 8 + 2 * tig + j;
            if (seg == 0 || seg == 2) {
                sv[nt][j] = g_sinv[cl];
                pp[nt][j] = g_pw[cl];
            }
            ch[nt][j] = cl >> 6;
            cd[nt][j] = cl & 63;
        }

#pragma unroll
    for (int mt = 0; mt < 4; mt++) {
#pragma unroll
        for (int ii = 0; ii < 2; ii++) {
            const int m = row0 + wm * 64 + mt * 16 + grp + ii * 8;
            const int b = m >> 12;
            const int n = m & 4095;
            if (seg == 0) {  // ---- q ----
#pragma unroll
                for (int nt = 0; nt < 4; nt++) {
                    float2 po, ne;
#pragma unroll
                    for (int j = 0; j < 2; j++) {
                        const float v = c[mt][nt][ii * 2 + j] * sv[nt][j];
                        const float p = pp[nt][j];
                        const float vp = fmaxf(v, 0.f), vn = fmaxf(-v, 0.f);
                        const float rp = (vp > 0.f) ? __powf(vp, p) : 0.f;
                        const float rn = (vn > 0.f) ? __powf(vn, p) : 0.f;
                        if (j == 0) { po.x = rp; ne.x = rn; }
                        else        { po.y = rp; ne.y = rn; }
                    }
                    const size_t base =
                        ((size_t)((b * NH_ + ch[nt][0]) * N_ + n)) * 128;
                    *(float2*)&g_QP[base + cd[nt][0]]      = po;
                    *(float2*)&g_QP[base + 64 + cd[nt][0]] = ne;
                }
            } else if (seg == 1) {  // ---- g ----
#pragma unroll
                for (int nt = 0; nt < 4; nt++) {
                    float2 o = make_float2(c[mt][nt][ii * 2],
                                           c[mt][nt][ii * 2 + 1]);
                    *(float2*)&g_G[(size_t)m * C_ + cbase + nt * 8 + 2 * tig] = o;
                }
            } else if (seg == 2) {  // ---- k ----
                const int nm = n % MAXP_;
#pragma unroll
                for (int nt = 0; nt < 4; nt++) {
                    float2 po, ne;
#pragma unroll
                    for (int j = 0; j < 2; j++) {
                        const int cl = cbase + nt * 8 + 2 * tig + j;
                        const float v = (c[mt][nt][ii * 2 + j] +
                                         pos_emb[(size_t)nm * C_ + cl]) *
                                        sv[nt][j];
                        const float p = pp[nt][j];
                        const float vp = fmaxf(v, 0.f), vn = fmaxf(-v, 0.f);
                        const float rp = (vp > 0.f) ? __powf(vp, p) : 0.f;
                        const float rn = (vn > 0.f) ? __powf(vn, p) : 0.f;
                        if (j == 0) { po.x = rp; ne.x = rn; }
                        else        { po.y = rp; ne.y = rn; }
                    }
                    const size_t base =
                        ((size_t)((b * NH_ + ch[nt][0]) * N_ + n)) * 128;
                    *(float2*)&g_KK[base + cd[nt][0]]      = po;
                    *(float2*)&g_KK[base + 64 + cd[nt][0]] = ne;
                }
            } else {  // ---- v ----
#pragma unroll
                for (int nt = 0; nt < 4; nt++) {
                    float2 o = make_float2(c[mt][nt][ii * 2],
                                           c[mt][nt][ii * 2 + 1]);
                    *(float2*)&g_V[((size_t)((b * NH_ + ch[nt][0]) * N_ + n)) *
                                       64 +
                                   cd[nt][0]] = o;
                }
            }
        }
    }
}

// ---------------------------------------------------------------------------
// GEMM 2: out = T @ proj_w.T + proj_b  (32768 x 512)
// ---------------------------------------------------------------------------
__global__ __launch_bounds__(256) void gemm_proj(
    const float* __restrict__ proj_w, const float* __restrict__ proj_b,
    float* __restrict__ out) {
    const int row0 = blockIdx.y * 128;
    const int col0 = blockIdx.x * 128;
    const float* __restrict__ Wp = proj_w + (size_t)col0 * C_;

    GEMM_CORE(g_T, Wp)

    const int cbase = col0 + wn * 32;
    float bv[4][2];
#pragma unroll
    for (int nt = 0; nt < 4; nt++) {
        bv[nt][0] = proj_b[cbase + nt * 8 + 2 * tig];
        bv[nt][1] = proj_b[cbase + nt * 8 + 2 * tig + 1];
    }

#pragma unroll
    for (int mt = 0; mt < 4; mt++)
#pragma unroll
        for (int ii = 0; ii < 2; ii++) {
            const int m = row0 + wm * 64 + mt * 16 + grp + ii * 8;
#pragma unroll
            for (int nt = 0; nt < 4; nt++) {
                float2 o = make_float2(c[mt][nt][ii * 2] + bv[nt][0],
                                       c[mt][nt][ii * 2 + 1] + bv[nt][1]);
                *(float2*)&out[(size_t)m * C_ + cbase + nt * 8 + 2 * tig] = o;
            }
        }
}

// ---------------------------------------------------------------------------
// KV reduction (pass 1): per (bh, chunk) partial sums of kk^T @ [v | 1]
// ---------------------------------------------------------------------------
__global__ __launch_bounds__(256) void kv_partial() {
    const int ch = blockIdx.x;
    const int bh = blockIdx.y;
    const int chunkN = N_ / NSPLIT;  // 512

    const float* KKp = g_KK + (size_t)bh * N_ * 128 + (size_t)ch * chunkN * 128;
    const float* Vp  = g_V  + (size_t)bh * N_ * 64  + (size_t)ch * chunkN * 64;

    __shared__ float skk[8][128];
    __shared__ float sv[8][64];

    const int t  = threadIdx.x;
    const int dg = t >> 2;
    const int eg = t & 3;
    const int d0 = dg * 2;
    const int eb = eg * 16;

    float acc0[16], acc1[16];
#pragma unroll
    for (int j = 0; j < 16; j++) { acc0[j] = 0.f; acc1[j] = 0.f; }
    float am0 = 0.f, am1 = 0.f;

    for (int n0 = 0; n0 < chunkN; n0 += 8) {
        __syncthreads();
        *(float4*)&skk[t >> 5][(t * 4) & 127] =
            *(const float4*)&KKp[(size_t)(n0 + (t >> 5)) * 128 + ((t * 4) & 127)];
        if (t < 128) {
            *(float4*)&sv[t >> 4][(t * 4) & 63] =
                *(const float4*)&Vp[(size_t)(n0 + (t >> 4)) * 64 + ((t * 4) & 63)];
        }
        __syncthreads();
#pragma unroll
        for (int nn = 0; nn < 8; nn++) {
            const float2 k2 = *(const float2*)&skk[nn][d0];
            am0 += k2.x; am1 += k2.y;
#pragma unroll
            for (int j4 = 0; j4 < 4; j4++) {
                const float4 vv = *(const float4*)&sv[nn][eb + j4 * 4];
                acc0[j4 * 4 + 0] += k2.x * vv.x; acc1[j4 * 4 + 0] += k2.y * vv.x;
                acc0[j4 * 4 + 1] += k2.x * vv.y; acc1[j4 * 4 + 1] += k2.y * vv.y;
                acc0[j4 * 4 + 2] += k2.x * vv.z; acc1[j4 * 4 + 2] += k2.y * vv.z;
                acc0[j4 * 4 + 3] += k2.x * vv.w; acc1[j4 * 4 + 3] += k2.y * vv.w;
            }
        }
    }

    float* P = g_PART + (size_t)(bh * NSPLIT + ch) * (128 * 65);
#pragma unroll
    for (int j = 0; j < 16; j++) {
        P[(d0 + 0) * 65 + eb + j] = acc0[j];
        P[(d0 + 1) * 65 + eb + j] = acc1[j];
    }
    if (eg == 0) {
        P[(d0 + 0) * 65 + 64] = am0;
        P[(d0 + 1) * 65 + 64] = am1;
    }
}

__global__ __launch_bounds__(256) void kv_reduce() {
    const int bh = blockIdx.x;
    for (int idx = threadIdx.x; idx < 128 * 65; idx += 256) {
        float s = 0.f;
#pragma unroll
        for (int c = 0; c < NSPLIT; c++)
            s += g_PART[(size_t)(bh * NSPLIT + c) * (128 * 65) + idx];
        g_KVALL[(size_t)bh * (128 * 65) + idx] = s * (1.0f / (float)N_);
    }
}

// ---------------------------------------------------------------------------
// Apply attention: xa = [q_sim@kv1 * z1 , q_opp@kv2 * z2] -> g_T (B,N,C)
// ---------------------------------------------------------------------------
__global__ __launch_bounds__(256) void attn_apply() {
    const int bh = blockIdx.y;
    const int b  = bh >> 3;
    const int h  = bh & 7;

    __shared__ float skv[128][68];
    for (int i = threadIdx.x; i < 128 * 65; i += 256) {
        const int d = i / 65, e = i % 65;
        skv[d][e] = g_KVALL[(size_t)bh * (128 * 65) + i];
    }
    __syncthreads();

    const int n = blockIdx.x * 256 + threadIdx.x;
    const float* Q = g_QP + ((size_t)bh * N_ + n) * 128;

    float accS[32], accO[32];
#pragma unroll
    for (int e = 0; e < 32; e++) { accS[e] = 0.f; accO[e] = 0.f; }
    float zs = 0.f, zo = 0.f;

    for (int d0 = 0; d0 < 64; d0 += 4) {
        float ql[4], qh[4];
        *(float4*)&ql[0] = *(const float4*)&Q[d0];
        *(float4*)&qh[0] = *(const float4*)&Q[d0 + 64];
#pragma unroll
        for (int dd = 0; dd < 4; dd++) {
            const int d = d0 + dd;
            const float a = ql[dd], bq = qh[dd];
            zs += a * skv[d][64]      + bq * skv[d + 64][64];
            zo += a * skv[d + 64][64] + bq * skv[d][64];
#pragma unroll
            for (int e4 = 0; e4 < 8; e4++) {
                const float4 v1 = *(const float4*)&skv[d][e4 * 4];
                const float4 v2 = *(const float4*)&skv[d + 64][e4 * 4];
                accS[e4 * 4 + 0] += a * v1.x + bq * v2.x;
                accS[e4 * 4 + 1] += a * v1.y + bq * v2.y;
                accS[e4 * 4 + 2] += a * v1.z + bq * v2.z;
                accS[e4 * 4 + 3] += a * v1.w + bq * v2.w;
                const float4 w1 = *(const float4*)&skv[d + 64][32 + e4 * 4];
                const float4 w2 = *(const float4*)&skv[d][32 + e4 * 4];
                accO[e4 * 4 + 0] += a * w1.x + bq * w2.x;
                accO[e4 * 4 + 1] += a * w1.y + bq * w2.y;
                accO[e4 * 4 + 2] += a * w1.z + bq * w2.z;
                accO[e4 * 4 + 3] += a * w1.w + bq * w2.w;
            }
        }
    }

    const float z1 = 1.0f / (zs + EPS_);
    const float z2 = 1.0f / (zo + EPS_);
    float* op = g_T + ((size_t)(b * N_ + n)) * C_ + h * 64;
#pragma unroll
    for (int e4 = 0; e4 < 8; e4++) {
        float4 o1 = make_float4(accS[e4 * 4 + 0] * z1, accS[e4 * 4 + 1] * z1,
                                accS[e4 * 4 + 2] * z1, accS[e4 * 4 + 3] * z1);
        *(float4*)&op[e4 * 4] = o1;
        float4 o2 = make_float4(accO[e4 * 4 + 0] * z2, accO[e4 * 4 + 1] * z2,
                                accO[e4 * 4 + 2] * z2, accO[e4 * 4 + 3] * z2);
        *(float4*)&op[32 + e4 * 4] = o2;
    }
}

// ---------------------------------------------------------------------------
// Depthwise 5x5 conv fused with t = (xa + vd + bias) * g, in-place in g_T.
// ---------------------------------------------------------------------------
__global__ __launch_bounds__(128) void conv_fuse(const float* __restrict__ dwc_w,
                                                 const float* __restrict__ dwc_b) {
    const int b  = blockIdx.z;
    const int hw = blockIdx.y;
    const int s0 = blockIdx.x * 64;
    const int nh     = hw >> 3;
    const int base_n = (hw & 7) << 9;
    const int t = threadIdx.x;

    __shared__ float tile[8][68][12];
    __shared__ float wsm[25];
    __shared__ float outs[512][8];

    if (t < 25) wsm[t] = dwc_w[hw * 25 + t];

    for (int rid = t; rid < 8 * 68; rid += 128) {
        const int q  = rid / 68;
        const int sr = rid % 68;
        const int y  = q * 512 + s0 - 2 + sr;
        float* dst = &tile[q][sr][0];
        dst[0] = 0.f; dst[1] = 0.f; dst[10] = 0.f; dst[11] = 0.f;
        if (y >= 0 && y < N_) {
            const float* src =
                g_V + ((size_t)((b * NH_ + nh) * N_ + base_n + (y >> 3))) * 64 +
                ((y & 7) << 3);
#pragma unroll
            for (int xx = 0; xx < 8; xx++) dst[2 + xx] = src[xx];
        } else {
#pragma unroll
            for (int xx = 0; xx < 8; xx++) dst[2 + xx] = 0.f;
        }
    }
    __syncthreads();

    const int q  = t & 7;
    const int sb = t >> 3;
#pragma unroll
    for (int i = 0; i < 4; i++) {
        const int s = sb * 4 + i;
        float o[8];
#pragma unroll
        for (int x = 0; x < 8; x++) o[x] = 0.f;
#pragma unroll
        for (int ky = 0; ky < 5; ky++) {
            const float4* rp = (const float4*)&tile[q][s + ky][0];
            const float4 ra = rp[0], rb = rp[1], rc = rp[2];
            const float r[12] = {ra.x, ra.y, ra.z, ra.w, rb.x, rb.y,
                                 rb.z, rb.w, rc.x, rc.y, rc.z, rc.w};
#pragma unroll
            for (int kx = 0; kx < 5; kx++) {
                const float wv = wsm[ky * 5 + kx];
#pragma unroll
                for (int x = 0; x < 8; x++) o[x] += wv * r[x + kx];
            }
        }
#pragma unroll
        for (int x = 0; x < 8; x++) outs[s * 8 + x][q] = o[x];
    }
    __syncthreads();

    const float bias = dwc_b[hw];
    const size_t rowbase = ((size_t)b * N_ + (size_t)s0 * 8) * C_ + hw * 8;
#pragma unroll
    for (int k = 0; k < 32; k++) {
        const int idx = t + k * 128;
        const int nr = idx >> 3, q2 = idx & 7;
        const size_t gidx = rowbase + (size_t)nr * C_ + q2;
        g_T[gidx] = (g_T[gidx] + outs[nr][q2] + bias) * g_G[gidx];
    }
}

// ---------------------------------------------------------------------------
// Launch
// ---------------------------------------------------------------------------
extern "C" void kernel_launch(void* const* d_in, const int* in_sizes, int n_in,
                              void* d_out, int out_size) {
    const float* x       = (const float*)d_in[0];
    const float* qg_w    = (const float*)d_in[1];
    const float* kv_w    = (const float*)d_in[2];
    const float* proj_w  = (const float*)d_in[3];
    const float* proj_b  = (const float*)d_in[4];
    const float* power_p = (const float*)d_in[5];
    const float* scale_p = (const float*)d_in[6];
    const float* pos_emb = (const float*)d_in[7];
    const float* dwc_w   = (const float*)d_in[8];
    const float* dwc_b   = (const float*)d_in[9];
    float* out = (float*)d_out;

    (void)in_sizes; (void)n_in; (void)out_size;

    setup_kernel<<<2, 256>>>(scale_p, power_p);
    gemm_qgkv<<<dim3(16, 256), 256>>>(x, qg_w, kv_w, pos_emb);
    kv_partial<<<dim3(NSPLIT, 64), 256>>>();
    kv_reduce<<<64, 256>>>();
    attn_apply<<<dim3(16, 64), 256>>>();
    conv_fuse<<<dim3(8, 64, 8), 128>>>(dwc_w, dwc_b);
    gemm_proj<<<dim3(4, 256), 256>>>(proj_w, proj_b, out);
}

// round 8
// speedup vs baseline: 1.9481x; 1.1407x over previous
#include <cuda_runtime.h>
#include <math.h>

// ---------------------------------------------------------------------------
// Problem constants (fixed shapes)
// ---------------------------------------------------------------------------
#define B_   8
#define N_   4096
#define C_   512
#define NH_  8
#define HD_  64
#define MAXP_ 321
#define EPS_ 1e-6f
#define NSPLIT 8

// ---------------------------------------------------------------------------
// Scratch (device globals — no allocations allowed)
// ---------------------------------------------------------------------------
__device__ float g_QP[33554432];          // (B,NH,N,128): q_pos | q_neg
__device__ float g_KK[33554432];          // (B,NH,N,128): k_pos | k_neg
__device__ float g_V [16777216];          // (B,NH,N,64)
__device__ float g_G [16777216];          // (B,N,C) gate
__device__ float g_T [16777216];          // (B,N,C): xa, then (xa+vd)*g
__device__ float g_PART[512 * 128 * 65];  // partial kv sums
__device__ float g_KVALL[64 * 128 * 65];  // (bh, d, e) e<64: kv, e=64: mean
__device__ float g_sinv[C_];              // 1/softplus(scale_p)
__device__ float g_pw[C_];                // 1 + 4*sigmoid(power_p)

// ---------------------------------------------------------------------------
// mma / cp.async helpers
// ---------------------------------------------------------------------------
__device__ __forceinline__ void mma_tf32(float c[4], unsigned a0, unsigned a1,
                                         unsigned a2, unsigned a3, unsigned b0,
                                         unsigned b1) {
    asm volatile(
        "mma.sync.aligned.m16n8k8.row.col.f32.tf32.tf32.f32 "
        "{%0,%1,%2,%3}, {%4,%5,%6,%7}, {%8,%9}, {%0,%1,%2,%3};"
        : "+f"(c[0]), "+f"(c[1]), "+f"(c[2]), "+f"(c[3])
        : "r"(a0), "r"(a1), "r"(a2), "r"(a3), "r"(b0), "r"(b1));
}

__device__ __forceinline__ void cpa16(unsigned dst, const void* src) {
    asm volatile("cp.async.cg.shared.global [%0], [%1], 16;" ::"r"(dst),
                 "l"(src));
}
__device__ __forceinline__ void cpa_commit() {
    asm volatile("cp.async.commit_group;");
}
__device__ __forceinline__ void cpa_wait0() {
    asm volatile("cp.async.wait_group 0;");
}

// ---------------------------------------------------------------------------
// Setup: per-channel scale / power
// ---------------------------------------------------------------------------
__global__ void setup_kernel(const float* __restrict__ scale_p,
                             const float* __restrict__ power_p) {
    int c = blockIdx.x * blockDim.x + threadIdx.x;
    if (c < C_) {
        g_sinv[c] = 1.0f / log1pf(expf(scale_p[c]));
        g_pw[c]   = 1.0f + 4.0f / (1.0f + expf(-power_p[c]));
    }
}

// ---------------------------------------------------------------------------
// Shared tf32 GEMM core v2 (128x128 block, KT=16 double-buffered via cp.async,
// 8 warps 64x32, fp32 bit patterns fed to tf32 mma = HW truncation).
// Computes C[m][n] = sum_k A[row0+m][k] * W[col0+n][k] into c[4][4][4].
// ---------------------------------------------------------------------------
#define GEMM_CORE(Aptr, Wptr)                                                  \
    __shared__ float As[2][128][20];                                           \
    __shared__ float Bs[2][128][20];                                           \
    const int tid  = threadIdx.x;                                              \
    const int lane = tid & 31;                                                 \
    const int grp  = lane >> 2;                                                \
    const int tig  = lane & 3;                                                 \
    const int wid  = tid >> 5;                                                 \
    const int wm   = wid >> 2;                                                 \
    const int wn   = wid & 3;                                                  \
    const int sr   = tid >> 1;                                                 \
    const int sk   = (tid & 1) * 8;                                            \
    const float* aG = (Aptr) + (size_t)(row0 + sr) * C_ + sk;                  \
    const float* bG = (Wptr) + (size_t)sr * C_ + sk;                           \
    const unsigned aS0 =                                                       \
        (unsigned)__cvta_generic_to_shared(&As[0][sr][sk]);                    \
    const unsigned aS1 =                                                       \
        (unsigned)__cvta_generic_to_shared(&As[1][sr][sk]);                    \
    const unsigned bS0 =                                                       \
        (unsigned)__cvta_generic_to_shared(&Bs[0][sr][sk]);                    \
    const unsigned bS1 =                                                       \
        (unsigned)__cvta_generic_to_shared(&Bs[1][sr][sk]);                    \
    float c[4][4][4];                                                          \
    _Pragma("unroll") for (int i = 0; i < 4; i++)                              \
        _Pragma("unroll") for (int j = 0; j < 4; j++)                          \
            _Pragma("unroll") for (int l = 0; l < 4; l++) c[i][j][l] = 0.f;    \
    cpa16(aS0, aG);                                                            \
    cpa16(aS0 + 16, aG + 4);                                                   \
    cpa16(bS0, bG);                                                            \
    cpa16(bS0 + 16, bG + 4);                                                   \
    cpa_commit();                                                              \
    cpa_wait0();                                                               \
    __syncthreads();                                                           \
    int buf = 0;                                                               \
    for (int kt = 0; kt < 32; kt++) {                                          \
        if (kt < 31) {                                                         \
            const float* an = aG + (kt + 1) * 16;                              \
            const float* bn = bG + (kt + 1) * 16;                              \
            const unsigned ad = (buf ? aS0 : aS1);                             \
            const unsigned bd = (buf ? bS0 : bS1);                             \
            cpa16(ad, an);                                                     \
            cpa16(ad + 16, an + 4);                                            \
            cpa16(bd, bn);                                                     \
            cpa16(bd + 16, bn + 4);                                            \
            cpa_commit();                                                      \
        }                                                                      \
        _Pragma("unroll") for (int ks = 0; ks < 2; ks++) {                     \
            unsigned af[4][4], bf[4][2];                                       \
            _Pragma("unroll") for (int mt = 0; mt < 4; mt++) {                 \
                const unsigned* p = (const unsigned*)                          \
                    &As[buf][wm * 64 + mt * 16 + grp][ks * 8 + tig];           \
                af[mt][0] = p[0];                                              \
                af[mt][1] = p[160];                                            \
                af[mt][2] = p[4];                                              \
                af[mt][3] = p[164];                                            \
            }                                                                  \
            _Pragma("unroll") for (int nt = 0; nt < 4; nt++) {                 \
                const unsigned* p = (const unsigned*)                          \
                    &Bs[buf][wn * 32 + nt * 8 + grp][ks * 8 + tig];            \
                bf[nt][0] = p[0];                                              \
                bf[nt][1] = p[4];                                              \
            }                                                                  \
            _Pragma("unroll") for (int mt = 0; mt < 4; mt++)                   \
                _Pragma("unroll") for (int nt = 0; nt < 4; nt++)               \
                    mma_tf32(c[mt][nt], af[mt][0], af[mt][1], af[mt][2],       \
                             af[mt][3], bf[nt][0], bf[nt][1]);                 \
        }                                                                      \
        if (kt < 31) cpa_wait0();                                              \
        __syncthreads();                                                       \
        buf ^= 1;                                                              \
    }

// ---------------------------------------------------------------------------
// GEMM 1: y = x @ [qg_w ; kv_w].T  (32768 x 2048), fused nonlinear epilogue.
// Column segments: [0,512)=q, [512,1024)=g, [1024,1536)=k, [1536,2048)=v
// ---------------------------------------------------------------------------
__global__ __launch_bounds__(256) void gemm_qgkv(
    const float* __restrict__ x, const float* __restrict__ qg_w,
    const float* __restrict__ kv_w, const float* __restrict__ pos_emb) {
    const int row0 = blockIdx.y * 128;
    const int col0 = blockIdx.x * 128;
    const float* __restrict__ Wp =
        (col0 < 1024) ? (qg_w + (size_t)col0 * C_)
                      : (kv_w + (size_t)(col0 - 1024) * C_);

    GEMM_CORE(x, Wp)

    const int seg   = col0 >> 9;  // 0:q 1:g 2:k 3:v
    const int cbase = (col0 & 511) + wn * 32;

    // per-thread columns: cl[nt][j]
    float sv[4][2], pp[4][2];
    int ch[4][2], cd[4][2];
#pragma unroll
    for (int nt = 0; nt < 4; nt++)
#pragma unroll
        for (int j = 0; j < 2; j++) {
            const int cl = cbase + nt * 8 + 2 * tig + j;
            if (seg == 0 || seg == 2) {
                sv[nt][j] = g_sinv[cl];
                pp[nt][j] = g_pw[cl];
            }
            ch[nt][j] = cl >> 6;
            cd[nt][j] = cl & 63;
        }

#pragma unroll
    for (int mt = 0; mt < 4; mt++) {
#pragma unroll
        for (int ii = 0; ii < 2; ii++) {
            const int m = row0 + wm * 64 + mt * 16 + grp + ii * 8;
            const int b = m >> 12;
            const int n = m & 4095;
            if (seg == 0) {  // ---- q ----
#pragma unroll
                for (int nt = 0; nt < 4; nt++) {
                    float2 po, ne;
#pragma unroll
                    for (int j = 0; j < 2; j++) {
                        const float v = c[mt][nt][ii * 2 + j] * sv[nt][j];
                        const float p = pp[nt][j];
                        const float vp = fmaxf(v, 0.f), vn = fmaxf(-v, 0.f);
                        const float rp = (vp > 0.f) ? __powf(vp, p) : 0.f;
                        const float rn = (vn > 0.f) ? __powf(vn, p) : 0.f;
                        if (j == 0) { po.x = rp; ne.x = rn; }
                        else        { po.y = rp; ne.y = rn; }
                    }
                    const size_t base =
                        ((size_t)((b * NH_ + ch[nt][0]) * N_ + n)) * 128;
                    *(float2*)&g_QP[base + cd[nt][0]]      = po;
                    *(float2*)&g_QP[base + 64 + cd[nt][0]] = ne;
                }
            } else if (seg == 1) {  // ---- g ----
#pragma unroll
                for (int nt = 0; nt < 4; nt++) {
                    float2 o = make_float2(c[mt][nt][ii * 2],
                                           c[mt][nt][ii * 2 + 1]);
                    *(float2*)&g_G[(size_t)m * C_ + cbase + nt * 8 + 2 * tig] = o;
                }
            } else if (seg == 2) {  // ---- k ----
                const int nm = n % MAXP_;
#pragma unroll
                for (int nt = 0; nt < 4; nt++) {
                    float2 po, ne;
#pragma unroll
                    for (int j = 0; j < 2; j++) {
                        const int cl = cbase + nt * 8 + 2 * tig + j;
                        const float v = (c[mt][nt][ii * 2 + j] +
                                         pos_emb[(size_t)nm * C_ + cl]) *
                                        sv[nt][j];
                        const float p = pp[nt][j];
                        const float vp = fmaxf(v, 0.f), vn = fmaxf(-v, 0.f);
                        const float rp = (vp > 0.f) ? __powf(vp, p) : 0.f;
                        const float rn = (vn > 0.f) ? __powf(vn, p) : 0.f;
                        if (j == 0) { po.x = rp; ne.x = rn; }
                        else        { po.y = rp; ne.y = rn; }
                    }
                    const size_t base =
                        ((size_t)((b * NH_ + ch[nt][0]) * N_ + n)) * 128;
                    *(float2*)&g_KK[base + cd[nt][0]]      = po;
                    *(float2*)&g_KK[base + 64 + cd[nt][0]] = ne;
                }
            } else {  // ---- v ----
#pragma unroll
                for (int nt = 0; nt < 4; nt++) {
                    float2 o = make_float2(c[mt][nt][ii * 2],
                                           c[mt][nt][ii * 2 + 1]);
                    *(float2*)&g_V[((size_t)((b * NH_ + ch[nt][0]) * N_ + n)) *
                                       64 +
                                   cd[nt][0]] = o;
                }
            }
        }
    }
}

// ---------------------------------------------------------------------------
// GEMM 2: out = T @ proj_w.T + proj_b  (32768 x 512)
// ---------------------------------------------------------------------------
__global__ __launch_bounds__(256) void gemm_proj(
    const float* __restrict__ proj_w, const float* __restrict__ proj_b,
    float* __restrict__ out) {
    const int row0 = blockIdx.y * 128;
    const int col0 = blockIdx.x * 128;
    const float* __restrict__ Wp = proj_w + (size_t)col0 * C_;

    GEMM_CORE(g_T, Wp)

    const int cbase = col0 + wn * 32;
    float bv[4][2];
#pragma unroll
    for (int nt = 0; nt < 4; nt++) {
        bv[nt][0] = proj_b[cbase + nt * 8 + 2 * tig];
        bv[nt][1] = proj_b[cbase + nt * 8 + 2 * tig + 1];
    }

#pragma unroll
    for (int mt = 0; mt < 4; mt++)
#pragma unroll
        for (int ii = 0; ii < 2; ii++) {
            const int m = row0 + wm * 64 + mt * 16 + grp + ii * 8;
#pragma unroll
            for (int nt = 0; nt < 4; nt++) {
                float2 o = make_float2(c[mt][nt][ii * 2] + bv[nt][0],
                                       c[mt][nt][ii * 2 + 1] + bv[nt][1]);
                *(float2*)&out[(size_t)m * C_ + cbase + nt * 8 + 2 * tig] = o;
            }
        }
}

// ---------------------------------------------------------------------------
// KV reduction (pass 1): per (bh, chunk) partial sums of kk^T @ [v | 1]
// ---------------------------------------------------------------------------
__global__ __launch_bounds__(256) void kv_partial() {
    const int ch = blockIdx.x;
    const int bh = blockIdx.y;
    const int chunkN = N_ / NSPLIT;  // 512

    const float* KKp = g_KK + (size_t)bh * N_ * 128 + (size_t)ch * chunkN * 128;
    const float* Vp  = g_V  + (size_t)bh * N_ * 64  + (size_t)ch * chunkN * 64;

    __shared__ float skk[8][128];
    __shared__ float sv[8][64];

    const int t  = threadIdx.x;
    const int dg = t >> 2;
    const int eg = t & 3;
    const int d0 = dg * 2;
    const int eb = eg * 16;

    float acc0[16], acc1[16];
#pragma unroll
    for (int j = 0; j < 16; j++) { acc0[j] = 0.f; acc1[j] = 0.f; }
    float am0 = 0.f, am1 = 0.f;

    for (int n0 = 0; n0 < chunkN; n0 += 8) {
        __syncthreads();
        *(float4*)&skk[t >> 5][(t * 4) & 127] =
            *(const float4*)&KKp[(size_t)(n0 + (t >> 5)) * 128 + ((t * 4) & 127)];
        if (t < 128) {
            *(float4*)&sv[t >> 4][(t * 4) & 63] =
                *(const float4*)&Vp[(size_t)(n0 + (t >> 4)) * 64 + ((t * 4) & 63)];
        }
        __syncthreads();
#pragma unroll
        for (int nn = 0; nn < 8; nn++) {
            const float2 k2 = *(const float2*)&skk[nn][d0];
            am0 += k2.x; am1 += k2.y;
#pragma unroll
            for (int j4 = 0; j4 < 4; j4++) {
                const float4 vv = *(const float4*)&sv[nn][eb + j4 * 4];
                acc0[j4 * 4 + 0] += k2.x * vv.x; acc1[j4 * 4 + 0] += k2.y * vv.x;
                acc0[j4 * 4 + 1] += k2.x * vv.y; acc1[j4 * 4 + 1] += k2.y * vv.y;
                acc0[j4 * 4 + 2] += k2.x * vv.z; acc1[j4 * 4 + 2] += k2.y * vv.z;
                acc0[j4 * 4 + 3] += k2.x * vv.w; acc1[j4 * 4 + 3] += k2.y * vv.w;
            }
        }
    }

    float* P = g_PART + (size_t)(bh * NSPLIT + ch) * (128 * 65);
#pragma unroll
    for (int j = 0; j < 16; j++) {
        P[(d0 + 0) * 65 + eb + j] = acc0[j];
        P[(d0 + 1) * 65 + eb + j] = acc1[j];
    }
    if (eg == 0) {
        P[(d0 + 0) * 65 + 64] = am0;
        P[(d0 + 1) * 65 + 64] = am1;
    }
}

__global__ __launch_bounds__(256) void kv_reduce() {
    const int bh = blockIdx.x;
    for (int idx = threadIdx.x; idx < 128 * 65; idx += 256) {
        float s = 0.f;
#pragma unroll
        for (int c = 0; c < NSPLIT; c++)
            s += g_PART[(size_t)(bh * NSPLIT + c) * (128 * 65) + idx];
        g_KVALL[(size_t)bh * (128 * 65) + idx] = s * (1.0f / (float)N_);
    }
}

// ---------------------------------------------------------------------------
// Apply attention: xa = [q_sim@kv1 * z1 , q_opp@kv2 * z2] -> g_T (B,N,C)
// ---------------------------------------------------------------------------
__global__ __launch_bounds__(256) void attn_apply() {
    const int bh = blockIdx.y;
    const int b  = bh >> 3;
    const int h  = bh & 7;

    __shared__ float skv[128][68];
    for (int i = threadIdx.x; i < 128 * 65; i += 256) {
        const int d = i / 65, e = i % 65;
        skv[d][e] = g_KVALL[(size_t)bh * (128 * 65) + i];
    }
    __syncthreads();

    const int n = blockIdx.x * 256 + threadIdx.x;
    const float* Q = g_QP + ((size_t)bh * N_ + n) * 128;

    float accS[32], accO[32];
#pragma unroll
    for (int e = 0; e < 32; e++) { accS[e] = 0.f; accO[e] = 0.f; }
    float zs = 0.f, zo = 0.f;

    for (int d0 = 0; d0 < 64; d0 += 4) {
        float ql[4], qh[4];
        *(float4*)&ql[0] = *(const float4*)&Q[d0];
        *(float4*)&qh[0] = *(const float4*)&Q[d0 + 64];
#pragma unroll
        for (int dd = 0; dd < 4; dd++) {
            const int d = d0 + dd;
            const float a = ql[dd], bq = qh[dd];
            zs += a * skv[d][64]      + bq * skv[d + 64][64];
            zo += a * skv[d + 64][64] + bq * skv[d][64];
#pragma unroll
            for (int e4 = 0; e4 < 8; e4++) {
                const float4 v1 = *(const float4*)&skv[d][e4 * 4];
                const float4 v2 = *(const float4*)&skv[d + 64][e4 * 4];
                accS[e4 * 4 + 0] += a * v1.x + bq * v2.x;
                accS[e4 * 4 + 1] += a * v1.y + bq * v2.y;
                accS[e4 * 4 + 2] += a * v1.z + bq * v2.z;
                accS[e4 * 4 + 3] += a * v1.w + bq * v2.w;
                const float4 w1 = *(const float4*)&skv[d + 64][32 + e4 * 4];
                const float4 w2 = *(const float4*)&skv[d][32 + e4 * 4];
                accO[e4 * 4 + 0] += a * w1.x + bq * w2.x;
                accO[e4 * 4 + 1] += a * w1.y + bq * w2.y;
                accO[e4 * 4 + 2] += a * w1.z + bq * w2.z;
                accO[e4 * 4 + 3] += a * w1.w + bq * w2.w;
            }
        }
    }

    const float z1 = 1.0f / (zs + EPS_);
    const float z2 = 1.0f / (zo + EPS_);
    float* op = g_T + ((size_t)(b * N_ + n)) * C_ + h * 64;
#pragma unroll
    for (int e4 = 0; e4 < 8; e4++) {
        float4 o1 = make_float4(accS[e4 * 4 + 0] * z1, accS[e4 * 4 + 1] * z1,
                                accS[e4 * 4 + 2] * z1, accS[e4 * 4 + 3] * z1);
        *(float4*)&op[e4 * 4] = o1;
        float4 o2 = make_float4(accO[e4 * 4 + 0] * z2, accO[e4 * 4 + 1] * z2,
                                accO[e4 * 4 + 2] * z2, accO[e4 * 4 + 3] * z2);
        *(float4*)&op[32 + e4 * 4] = o2;
    }
}

// ---------------------------------------------------------------------------
// Depthwise 5x5 conv fused with t = (xa + vd + bias) * g, in-place in g_T.
// ---------------------------------------------------------------------------
__global__ __launch_bounds__(128) void conv_fuse(const float* __restrict__ dwc_w,
                                                 const float* __restrict__ dwc_b) {
    const int b  = blockIdx.z;
    const int hw = blockIdx.y;
    const int s0 = blockIdx.x * 64;
    const int nh     = hw >> 3;
    const int base_n = (hw & 7) << 9;
    const int t = threadIdx.x;

    __shared__ float tile[8][68][12];
    __shared__ float wsm[25];
    __shared__ float outs[512][8];

    if (t < 25) wsm[t] = dwc_w[hw * 25 + t];

    for (int rid = t; rid < 8 * 68; rid += 128) {
        const int q  = rid / 68;
        const int sr = rid % 68;
        const int y  = q * 512 + s0 - 2 + sr;
        float* dst = &tile[q][sr][0];
        dst[0] = 0.f; dst[1] = 0.f; dst[10] = 0.f; dst[11] = 0.f;
        if (y >= 0 && y < N_) {
            const float* src =
                g_V + ((size_t)((b * NH_ + nh) * N_ + base_n + (y >> 3))) * 64 +
                ((y & 7) << 3);
#pragma unroll
            for (int xx = 0; xx < 8; xx++) dst[2 + xx] = src[xx];
        } else {
#pragma unroll
            for (int xx = 0; xx < 8; xx++) dst[2 + xx] = 0.f;
        }
    }
    __syncthreads();

    const int q  = t & 7;
    const int sb = t >> 3;
#pragma unroll
    for (int i = 0; i < 4; i++) {
        const int s = sb * 4 + i;
        float o[8];
#pragma unroll
        for (int x = 0; x < 8; x++) o[x] = 0.f;
#pragma unroll
        for (int ky = 0; ky < 5; ky++) {
            const float4* rp = (const float4*)&tile[q][s + ky][0];
            const float4 ra = rp[0], rb = rp[1], rc = rp[2];
            const float r[12] = {ra.x, ra.y, ra.z, ra.w, rb.x, rb.y,
                                 rb.z, rb.w, rc.x, rc.y, rc.z, rc.w};
#pragma unroll
            for (int kx = 0; kx < 5; kx++) {
                const float wv = wsm[ky * 5 + kx];
#pragma unroll
                for (int x = 0; x < 8; x++) o[x] += wv * r[x + kx];
            }
        }
#pragma unroll
        for (int x = 0; x < 8; x++) outs[s * 8 + x][q] = o[x];
    }
    __syncthreads();

    const float bias = dwc_b[hw];
    const size_t rowbase = ((size_t)b * N_ + (size_t)s0 * 8) * C_ + hw * 8;
#pragma unroll
    for (int k = 0; k < 32; k++) {
        const int idx = t + k * 128;
        const int nr = idx >> 3, q2 = idx & 7;
        const size_t gidx = rowbase + (size_t)nr * C_ + q2;
        g_T[gidx] = (g_T[gidx] + outs[nr][q2] + bias) * g_G[gidx];
    }
}

// ---------------------------------------------------------------------------
// Launch
// ---------------------------------------------------------------------------
extern "C" void kernel_launch(void* const* d_in, const int* in_sizes, int n_in,
                              void* d_out, int out_size) {
    const float* x       = (const float*)d_in[0];
    const float* qg_w    = (const float*)d_in[1];
    const float* kv_w    = (const float*)d_in[2];
    const float* proj_w  = (const float*)d_in[3];
    const float* proj_b  = (const float*)d_in[4];
    const float* power_p = (const float*)d_in[5];
    const float* scale_p = (const float*)d_in[6];
    const float* pos_emb = (const float*)d_in[7];
    const float* dwc_w   = (const float*)d_in[8];
    const float* dwc_b   = (const float*)d_in[9];
    float* out = (float*)d_out;

    (void)in_sizes; (void)n_in; (void)out_size;

    setup_kernel<<<2, 256>>>(scale_p, power_p);
    gemm_qgkv<<<dim3(16, 256), 256>>>(x, qg_w, kv_w, pos_emb);
    kv_partial<<<dim3(NSPLIT, 64), 256>>>();
    kv_reduce<<<64, 256>>>();
    attn_apply<<<dim3(16, 64), 256>>>();
    conv_fuse<<<dim3(8, 64, 8), 128>>>(dwc_w, dwc_b);
    gemm_proj<<<dim3(4, 256), 256>>>(proj_w, proj_b, out);
}